// round 12
// baseline (speedup 1.0000x reference)
#include <cuda_runtime.h>
#include <cuda_fp16.h>
#include <math.h>
#include <stdint.h>

#define TOK 100352
#define SCALE 0.17677669529663687f

__device__ float  g_x[19267584];        // fp32 residual stream
__device__ __half g_hwin[19267584];
__device__ __half g_q[19267584];
__device__ __half g_k[19267584];
__device__ __half g_v[19267584];
__device__ __half g_attnout[19267584];
__device__ __half g_ln2[19267584];
__device__ __half g_hid[77070336];
__device__ __half g_wcv[884736];        // fp16 weights: qkv|proj|f1|f2 (both layers)

__device__ __forceinline__ float warp_sum(float v) {
#pragma unroll
    for (int o = 16; o; o >>= 1) v += __shfl_xor_sync(0xffffffffu, v, o);
    return v;
}
__device__ __forceinline__ uint32_t smem_u32(const void* p) {
    uint32_t a;
    asm("{ .reg .u64 t; cvta.to.shared.u64 t, %1; cvt.u32.u64 %0, t; }" : "=r"(a) : "l"(p));
    return a;
}
__device__ __forceinline__ void cpa16(uint32_t dst, const void* src) {
    asm volatile("cp.async.cg.shared.global [%0], [%1], 16;" :: "r"(dst), "l"(src));
}
__device__ __forceinline__ void mma16816(float* c, uint32_t a0, uint32_t a1, uint32_t a2, uint32_t a3,
                                         uint32_t b0, uint32_t b1) {
    asm volatile(
        "mma.sync.aligned.m16n8k16.row.col.f32.f16.f16.f32 "
        "{%0,%1,%2,%3}, {%4,%5,%6,%7}, {%8,%9}, {%0,%1,%2,%3};\n"
        : "+f"(c[0]), "+f"(c[1]), "+f"(c[2]), "+f"(c[3])
        : "r"(a0), "r"(a1), "r"(a2), "r"(a3), "r"(b0), "r"(b1));
}

// ---------------- weight pre-convert (fp32 -> fp16) ----------------
__global__ void convw_kernel(const float* __restrict__ s, __half* __restrict__ d, int n4) {
    int i = blockIdx.x * blockDim.x + threadIdx.x;
    if (i >= n4) return;
    float4 v = ((const float4*)s)[i];
    __half2* dp = (__half2*)d + i * 2;
    dp[0] = __floats2half2_rn(v.x, v.y);
    dp[1] = __floats2half2_rn(v.z, v.w);
}

// ---------------- LN kernels (fp16 outputs) ----------------
__global__ void ln1_part_kernel(const float* __restrict__ w, const float* __restrict__ b,
                                int shift, const float* __restrict__ xin) {
    int gw = (blockIdx.x * blockDim.x + threadIdx.x) >> 5;
    int lane = threadIdx.x & 31;
    if (gw >= TOK) return;
    int win = gw / 49, tok = gw % 49;
    int bb = win >> 6, w64 = win & 63;
    int wh = w64 >> 3, wwi = w64 & 7;
    int ii = tok / 7, jj = tok % 7;
    int sh = (wh * 7 + ii + shift) % 56;
    int sw = (wwi * 7 + jj + shift) % 56;
    const float* base = xin ? xin : g_x;
    const float* src = base + ((size_t)bb * 3136 + sh * 56 + sw) * 192;
    float v[6];
    float s = 0.f;
#pragma unroll
    for (int q = 0; q < 6; q++) { v[q] = src[lane + q * 32]; s += v[q]; }
    s = warp_sum(s);
    float mean = s * (1.f / 192.f);
    float ss = 0.f;
#pragma unroll
    for (int q = 0; q < 6; q++) { float d = v[q] - mean; ss += d * d; }
    ss = warp_sum(ss);
    float rstd = rsqrtf(ss * (1.f / 192.f) + 1e-5f);
    __half* dst = g_hwin + (size_t)gw * 192;
#pragma unroll
    for (int q = 0; q < 6; q++) {
        int c = lane + q * 32;
        dst[c] = __float2half((v[q] - mean) * rstd * w[c] + b[c]);
    }
}

__global__ void ln2_kernel(const float* __restrict__ w, const float* __restrict__ b) {
    int gw = (blockIdx.x * blockDim.x + threadIdx.x) >> 5;
    int lane = threadIdx.x & 31;
    if (gw >= TOK) return;
    const float* src = g_x + (size_t)gw * 192;
    float v[6];
    float s = 0.f;
#pragma unroll
    for (int q = 0; q < 6; q++) { v[q] = src[lane + q * 32]; s += v[q]; }
    s = warp_sum(s);
    float mean = s * (1.f / 192.f);
    float ss = 0.f;
#pragma unroll
    for (int q = 0; q < 6; q++) { float d = v[q] - mean; ss += d * d; }
    ss = warp_sum(ss);
    float rstd = rsqrtf(ss * (1.f / 192.f) + 1e-5f);
    __half* dst = g_ln2 + (size_t)gw * 192;
#pragma unroll
    for (int q = 0; q < 6; q++) {
        int c = lane + q * 32;
        dst[c] = __float2half((v[q] - mean) * rstd * w[c] + b[c]);
    }
}

__device__ __forceinline__ int reg3(int h) { return h < 49 ? 0 : (h < 53 ? 1 : 2); }

// ---------------- tensor-core attention: one (window, head) per 128-thread CTA ----------------
__global__ void __launch_bounds__(128) attn_kernel(const float* __restrict__ rpb, int shift) {
    __shared__ __half q_sm[64 * 72];
    __shared__ __half k_sm[56 * 72];
    __shared__ __half vt_sm[32 * 72];
    __shared__ __half p_sm[64 * 72];
    __shared__ float bias_sm[169];
    int bid = blockIdx.x;
    int win = bid / 6, head = bid % 6;
    int tid = threadIdx.x;
    const __half* qg = g_q + (size_t)bid * 1568;
    const __half* kg = g_k + (size_t)bid * 1568;
    const __half* vg = g_v + (size_t)bid * 1568;

    // phase 1: zero P, Vt, and q padding rows (padding correctness)
    for (int i2 = tid; i2 < 64 * 36; i2 += 128) ((uint32_t*)p_sm)[i2] = 0;
    for (int i2 = tid; i2 < 32 * 36; i2 += 128) ((uint32_t*)vt_sm)[i2] = 0;
    for (int i2 = 49 * 36 + tid; i2 < 64 * 36; i2 += 128) ((uint32_t*)q_sm)[i2] = 0;
    __syncthreads();

    // phase 2: fill q, k (vectorized), v transposed, bias table
    for (int idx = tid; idx < 392; idx += 128) {
        int row = idx >> 3, d0 = (idx & 7) * 4;
        *(uint2*)&q_sm[row * 72 + d0] = *(const uint2*)&qg[idx * 4];
        *(uint2*)&k_sm[row * 72 + d0] = *(const uint2*)&kg[idx * 4];
    }
    for (int idx = tid; idx < 1568; idx += 128) {
        int j = idx >> 5, d = idx & 31;
        vt_sm[d * 72 + j] = vg[idx];
    }
    for (int idx = tid; idx < 169; idx += 128) bias_sm[idx] = rpb[idx * 6 + head];
    __syncthreads();

    const int wid = tid >> 5, lane = tid & 31;
    const int g = lane >> 2, tg = lane & 3;
    const int i0 = 16 * wid + g, i1 = i0 + 8;

    // S = q @ k^T : 7 n8-tiles, 2 k16-steps
    float c[7][4];
#pragma unroll
    for (int t = 0; t < 7; t++) { c[t][0] = c[t][1] = c[t][2] = c[t][3] = 0.f; }
#pragma unroll
    for (int s = 0; s < 2; s++) {
        uint32_t a0 = *(uint32_t*)&q_sm[i0 * 72 + 2 * tg + 16 * s];
        uint32_t a1 = *(uint32_t*)&q_sm[i1 * 72 + 2 * tg + 16 * s];
        uint32_t a2 = *(uint32_t*)&q_sm[i0 * 72 + 2 * tg + 8 + 16 * s];
        uint32_t a3 = *(uint32_t*)&q_sm[i1 * 72 + 2 * tg + 8 + 16 * s];
#pragma unroll
        for (int t = 0; t < 7; t++) {
            uint32_t b0 = *(uint32_t*)&k_sm[(8 * t + g) * 72 + 2 * tg + 16 * s];
            uint32_t b1 = *(uint32_t*)&k_sm[(8 * t + g) * 72 + 2 * tg + 8 + 16 * s];
            mma16816(c[t], a0, a1, a2, a3, b0, b1);
        }
    }

    // bias + mask + softmax
    int w64 = win & 63, wh = w64 >> 3, wwi = w64 & 7;
    int ic0 = i0 < 49 ? i0 : 48, ic1 = i1 < 49 ? i1 : 48;
    int yi0 = ic0 / 7, xi0 = ic0 % 7, yi1 = ic1 / 7, xi1 = ic1 % 7;
    int ri0 = 0, ri1 = 0;
    if (shift) {
        ri0 = reg3(wh * 7 + yi0) * 3 + reg3(wwi * 7 + xi0);
        ri1 = reg3(wh * 7 + yi1) * 3 + reg3(wwi * 7 + xi1);
    }
    float v0[7][2], v1[7][2];
#pragma unroll
    for (int t = 0; t < 7; t++) {
#pragma unroll
        for (int e = 0; e < 2; e++) {
            int j = 8 * t + 2 * tg + e;
            bool valid = j < 49;
            int jc = valid ? j : 0;
            int yj = jc / 7, xj = jc % 7;
            float m0 = 0.f, m1 = 0.f;
            if (shift) {
                int rj = reg3(wh * 7 + yj) * 3 + reg3(wwi * 7 + xj);
                if (ri0 != rj) m0 = -100.f;
                if (ri1 != rj) m1 = -100.f;
            }
            float b0 = bias_sm[(yi0 - yj + 6) * 13 + (xi0 - xj + 6)];
            float b1 = bias_sm[(yi1 - yj + 6) * 13 + (xi1 - xj + 6)];
            v0[t][e] = valid ? c[t][e] + b0 + m0 : -1e9f;
            v1[t][e] = valid ? c[t][2 + e] + b1 + m1 : -1e9f;
        }
    }
    float mx0 = -1e30f, mx1 = -1e30f;
#pragma unroll
    for (int t = 0; t < 7; t++) {
        mx0 = fmaxf(mx0, fmaxf(v0[t][0], v0[t][1]));
        mx1 = fmaxf(mx1, fmaxf(v1[t][0], v1[t][1]));
    }
    mx0 = fmaxf(mx0, __shfl_xor_sync(0xffffffffu, mx0, 1));
    mx0 = fmaxf(mx0, __shfl_xor_sync(0xffffffffu, mx0, 2));
    mx1 = fmaxf(mx1, __shfl_xor_sync(0xffffffffu, mx1, 1));
    mx1 = fmaxf(mx1, __shfl_xor_sync(0xffffffffu, mx1, 2));
    float sm0 = 0.f, sm1 = 0.f;
#pragma unroll
    for (int t = 0; t < 7; t++) {
#pragma unroll
        for (int e = 0; e < 2; e++) {
            v0[t][e] = __expf(v0[t][e] - mx0); sm0 += v0[t][e];
            v1[t][e] = __expf(v1[t][e] - mx1); sm1 += v1[t][e];
        }
    }
    sm0 += __shfl_xor_sync(0xffffffffu, sm0, 1);
    sm0 += __shfl_xor_sync(0xffffffffu, sm0, 2);
    sm1 += __shfl_xor_sync(0xffffffffu, sm1, 1);
    sm1 += __shfl_xor_sync(0xffffffffu, sm1, 2);
    float inv0 = 1.f / sm0, inv1 = 1.f / sm1;
#pragma unroll
    for (int t = 0; t < 7; t++) {
        *(__half2*)&p_sm[i0 * 72 + 8 * t + 2 * tg] = __floats2half2_rn(v0[t][0] * inv0, v0[t][1] * inv0);
        *(__half2*)&p_sm[i1 * 72 + 8 * t + 2 * tg] = __floats2half2_rn(v1[t][0] * inv1, v1[t][1] * inv1);
    }
    __syncthreads();

    // O = P @ V : 4 n8-tiles (d), 4 k16-steps (j)
    float o[4][4];
#pragma unroll
    for (int t = 0; t < 4; t++) { o[t][0] = o[t][1] = o[t][2] = o[t][3] = 0.f; }
#pragma unroll
    for (int s = 0; s < 4; s++) {
        uint32_t a0 = *(uint32_t*)&p_sm[i0 * 72 + 2 * tg + 16 * s];
        uint32_t a1 = *(uint32_t*)&p_sm[i1 * 72 + 2 * tg + 16 * s];
        uint32_t a2 = *(uint32_t*)&p_sm[i0 * 72 + 2 * tg + 8 + 16 * s];
        uint32_t a3 = *(uint32_t*)&p_sm[i1 * 72 + 2 * tg + 8 + 16 * s];
#pragma unroll
        for (int t = 0; t < 4; t++) {
            uint32_t b0 = *(uint32_t*)&vt_sm[(8 * t + g) * 72 + 2 * tg + 16 * s];
            uint32_t b1 = *(uint32_t*)&vt_sm[(8 * t + g) * 72 + 2 * tg + 8 + 16 * s];
            mma16816(o[t], a0, a1, a2, a3, b0, b1);
        }
    }
    if (i0 < 49) {
        __half* dst = g_attnout + ((size_t)(win * 49 + i0)) * 192 + head * 32;
#pragma unroll
        for (int t = 0; t < 4; t++)
            *(__half2*)&dst[8 * t + 2 * tg] = __floats2half2_rn(o[t][0], o[t][1]);
    }
    if (i1 < 49) {
        __half* dst = g_attnout + ((size_t)(win * 49 + i1)) * 192 + head * 32;
#pragma unroll
        for (int t = 0; t < 4; t++)
            *(__half2*)&dst[8 * t + 2 * tg] = __floats2half2_rn(o[t][2], o[t][3]);
    }
}

// -------- fp16 mma.sync GEMM: CTA 256x64, 128 threads, warp tile 64x64, 2-stage cp.async --------
// grid = (Ntiles, Mtiles): N-tiles of one M-tile adjacent -> A tile served from L2.
#define GT_DSMEM 51200

template <int MODE>
__global__ void __launch_bounds__(128) gemm_tc(const __half* __restrict__ Wt,
                                               const float* __restrict__ bias,
                                               int K, int shift,
                                               const float* __restrict__ xin,
                                               float* __restrict__ outp) {
    extern __shared__ unsigned sm[];
    const __half* A = (MODE == 0) ? g_hwin : (MODE == 1) ? g_attnout : (MODE == 2) ? g_ln2 : g_hid;
    const int bm = blockIdx.y * 256;
    const int bn = blockIdx.x * 64;
    const int tid = threadIdx.x, wid = tid >> 5, lane = tid & 31;
    const int g = lane >> 2, tg = lane & 3;
    const uint32_t sbase = smem_u32(sm);
    const __half* Abase = A + (size_t)bm * K;
    const __half* Bbase = Wt + (size_t)bn * K;
    const int NCH = K >> 5;

    float acc[4][8][4];
#pragma unroll
    for (int i = 0; i < 4; i++)
#pragma unroll
        for (int j = 0; j < 8; j++)
#pragma unroll
            for (int r = 0; r < 4; r++) acc[i][j][r] = 0.f;

    auto issue = [&](int c) {
        uint32_t sb = sbase + (c & 1) * 25600;
        const __half* Ab = Abase + c * 32;
#pragma unroll
        for (int i = 0; i < 8; i++) {
            int f8 = tid + i * 128, row = f8 >> 2, ch = f8 & 3;
            cpa16(sb + (row * 20 + ch * 4) * 4, Ab + (size_t)row * K + ch * 8);
        }
        const __half* Bb = Bbase + c * 32;
#pragma unroll
        for (int i = 0; i < 2; i++) {
            int f8 = tid + i * 128, row = f8 >> 2, ch = f8 & 3;
            cpa16(sb + 20480 + (row * 20 + ch * 4) * 4, Bb + (size_t)row * K + ch * 8);
        }
        asm volatile("cp.async.commit_group;" ::: "memory");
    };

    issue(0);
    if (NCH > 1) issue(1);

    for (int c = 0; c < NCH; c++) {
        if (c + 1 < NCH) asm volatile("cp.async.wait_group 1;" ::: "memory");
        else             asm volatile("cp.async.wait_group 0;" ::: "memory");
        __syncthreads();
        const unsigned* as = sm + (c & 1) * 6400;
        const unsigned* bs = as + 5120;
#pragma unroll
        for (int s = 0; s < 2; s++) {
            const int k0 = s * 8 + tg;
            unsigned af[4][4], bf[8][2];
#pragma unroll
            for (int mt = 0; mt < 4; mt++) {
                int rb = wid * 64 + mt * 16 + g;
                af[mt][0] = as[rb * 20 + k0];
                af[mt][1] = as[(rb + 8) * 20 + k0];
                af[mt][2] = as[rb * 20 + k0 + 4];
                af[mt][3] = as[(rb + 8) * 20 + k0 + 4];
            }
#pragma unroll
            for (int nt = 0; nt < 8; nt++) {
                int nb = nt * 8 + g;
                bf[nt][0] = bs[nb * 20 + k0];
                bf[nt][1] = bs[nb * 20 + k0 + 4];
            }
#pragma unroll
            for (int mt = 0; mt < 4; mt++)
#pragma unroll
                for (int nt = 0; nt < 8; nt++)
                    mma16816(acc[mt][nt], af[mt][0], af[mt][1], af[mt][2], af[mt][3],
                             bf[nt][0], bf[nt][1]);
        }
        __syncthreads();
        if (c + 2 < NCH) issue(c + 2);
    }

#pragma unroll
    for (int mt = 0; mt < 4; mt++)
#pragma unroll
        for (int rr = 0; rr < 2; rr++) {
            int m = bm + wid * 64 + mt * 16 + g + rr * 8;
            if (MODE == 0) {
                int win = m / 49, tok = m % 49;
#pragma unroll
                for (int nt = 0; nt < 8; nt++) {
                    int c0 = nt * 8 + tg * 2;
                    int n = bn + c0;
                    int part = n / 192, rem = n % 192, head = rem >> 5, dd = rem & 31;
                    size_t dst = ((size_t)(win * 6 + head) * 49 + tok) * 32 + dd;
                    float v0 = acc[mt][nt][rr * 2] + bias[n];
                    float v1 = acc[mt][nt][rr * 2 + 1] + bias[n + 1];
                    if (part == 0)      *(__half2*)(g_q + dst) = __floats2half2_rn(v0 * SCALE, v1 * SCALE);
                    else if (part == 1) *(__half2*)(g_k + dst) = __floats2half2_rn(v0, v1);
                    else                *(__half2*)(g_v + dst) = __floats2half2_rn(v0, v1);
                }
            } else if (MODE == 1) {
                int win = m / 49, tok = m % 49;
                int bb = win >> 6, w64 = win & 63, wh = w64 >> 3, wwi = w64 & 7;
                int ii = tok / 7, jj = tok % 7;
                int hh = wh * 7 + ii, gc = wwi * 7 + jj;
                if (shift) { hh = (hh + 7) % 56; gc = (gc + 7) % 56; }
                size_t rowo = ((size_t)bb * 3136 + hh * 56 + gc) * 192 + bn;
                const float* resp = (xin ? xin : (const float*)g_x) + rowo;
#pragma unroll
                for (int nt = 0; nt < 8; nt++) {
                    int c0 = nt * 8 + tg * 2;
                    float2 rv = *(const float2*)(resp + c0);
                    float2 bv = *(const float2*)(bias + bn + c0);
                    float v0 = acc[mt][nt][rr * 2] + bv.x + rv.x;
                    float v1 = acc[mt][nt][rr * 2 + 1] + bv.y + rv.y;
                    *(float2*)(g_x + rowo + c0) = make_float2(v0, v1);
                }
            } else if (MODE == 2) {
                __half* hrow = g_hid + (size_t)m * 768 + bn;
#pragma unroll
                for (int nt = 0; nt < 8; nt++) {
                    int c0 = nt * 8 + tg * 2;
                    float2 bv = *(const float2*)(bias + bn + c0);
                    float v0 = acc[mt][nt][rr * 2] + bv.x;
                    float v1 = acc[mt][nt][rr * 2 + 1] + bv.y;
                    v0 = v0 * 0.5f * (1.f + erff(v0 * 0.70710678118654752f));
                    v1 = v1 * 0.5f * (1.f + erff(v1 * 0.70710678118654752f));
                    *(__half2*)(hrow + c0) = __floats2half2_rn(v0, v1);
                }
            } else {
                size_t rowo = (size_t)m * 192 + bn;
                float* dst = outp ? outp : g_x;
#pragma unroll
                for (int nt = 0; nt < 8; nt++) {
                    int c0 = nt * 8 + tg * 2;
                    float2 rv = *(const float2*)(g_x + rowo + c0);
                    float2 bv = *(const float2*)(bias + bn + c0);
                    float v0 = acc[mt][nt][rr * 2] + bv.x + rv.x;
                    float v1 = acc[mt][nt][rr * 2 + 1] + bv.y + rv.y;
                    *(float2*)(dst + rowo + c0) = make_float2(v0, v1);
                }
            }
        }
}

extern "C" void kernel_launch(void* const* d_in, const int* in_sizes, int n_in,
                              void* d_out, int out_size) {
    const float* x     = (const float*)d_in[0];
    const float* n1w   = (const float*)d_in[1];
    const float* n1b   = (const float*)d_in[2];
    const float* qkvw  = (const float*)d_in[3];
    const float* qkvb  = (const float*)d_in[4];
    const float* rpb   = (const float*)d_in[5];
    const float* projw = (const float*)d_in[6];
    const float* projb = (const float*)d_in[7];
    const float* n2w   = (const float*)d_in[8];
    const float* n2b   = (const float*)d_in[9];
    const float* f1w   = (const float*)d_in[10];
    const float* f1b   = (const float*)d_in[11];
    const float* f2w   = (const float*)d_in[12];
    const float* f2b   = (const float*)d_in[13];

    cudaFuncSetAttribute(gemm_tc<0>, cudaFuncAttributeMaxDynamicSharedMemorySize, GT_DSMEM);
    cudaFuncSetAttribute(gemm_tc<1>, cudaFuncAttributeMaxDynamicSharedMemorySize, GT_DSMEM);
    cudaFuncSetAttribute(gemm_tc<2>, cudaFuncAttributeMaxDynamicSharedMemorySize, GT_DSMEM);
    cudaFuncSetAttribute(gemm_tc<3>, cudaFuncAttributeMaxDynamicSharedMemorySize, GT_DSMEM);

    __half* wq = nullptr; cudaGetSymbolAddress((void**)&wq, g_wcv);
    __half* wp = wq + 221184;
    __half* w1 = wq + 294912;
    __half* w2 = wq + 589824;
    convw_kernel<<<216, 256>>>(qkvw,  wq, 55296);
    convw_kernel<<<72,  256>>>(projw, wp, 18432);
    convw_kernel<<<288, 256>>>(f1w,   w1, 73728);
    convw_kernel<<<288, 256>>>(f2w,   w2, 73728);

    for (int d = 0; d < 2; d++) {
        int shift = d ? 3 : 0;
        const float* xin = (d == 0) ? x : nullptr;
        float* outp = (d == 1) ? (float*)d_out : nullptr;
        ln1_part_kernel<<<12544, 256>>>(n1w + d * 192, n1b + d * 192, shift, xin);
        gemm_tc<0><<<dim3(9, 392), 128, GT_DSMEM>>>(wq + (size_t)d * 110592, qkvb + d * 576, 192, 0, nullptr, nullptr);
        attn_kernel<<<12288, 128>>>(rpb + d * 169 * 6, shift);
        gemm_tc<1><<<dim3(3, 392), 128, GT_DSMEM>>>(wp + (size_t)d * 36864, projb + d * 192, 192, shift, xin, nullptr);
        ln2_kernel<<<12544, 256>>>(n2w + d * 192, n2b + d * 192);
        gemm_tc<2><<<dim3(12, 392), 128, GT_DSMEM>>>(w1 + (size_t)d * 147456, f1b + d * 768, 192, 0, nullptr, nullptr);
        gemm_tc<3><<<dim3(3, 392), 128, GT_DSMEM>>>(w2 + (size_t)d * 147456, f2b + d * 192, 768, 0, nullptr, outp);
    }
}

// round 13
// speedup vs baseline: 1.0265x; 1.0265x over previous
#include <cuda_runtime.h>
#include <cuda_fp16.h>
#include <math.h>
#include <stdint.h>

#define TOK 100352
#define SCALE 0.17677669529663687f

__device__ float  g_x[19267584];        // fp32 residual stream
__device__ __half g_hwin[19267584];
__device__ __half g_q[19267584];
__device__ __half g_k[19267584];
__device__ __half g_v[19267584];
__device__ __half g_attnout[19267584];
__device__ __half g_ln2[19267584];
__device__ __half g_hid[77070336];
__device__ __half g_wcv[884736];        // fp16 weights: qkv|proj|f1|f2 (both layers)

__device__ __forceinline__ float warp_sum(float v) {
#pragma unroll
    for (int o = 16; o; o >>= 1) v += __shfl_xor_sync(0xffffffffu, v, o);
    return v;
}
__device__ __forceinline__ uint32_t smem_u32(const void* p) {
    uint32_t a;
    asm("{ .reg .u64 t; cvta.to.shared.u64 t, %1; cvt.u32.u64 %0, t; }" : "=r"(a) : "l"(p));
    return a;
}
__device__ __forceinline__ void cpa16(uint32_t dst, const void* src) {
    asm volatile("cp.async.cg.shared.global [%0], [%1], 16;" :: "r"(dst), "l"(src));
}
__device__ __forceinline__ void mma16816(float* c, uint32_t a0, uint32_t a1, uint32_t a2, uint32_t a3,
                                         uint32_t b0, uint32_t b1) {
    asm volatile(
        "mma.sync.aligned.m16n8k16.row.col.f32.f16.f16.f32 "
        "{%0,%1,%2,%3}, {%4,%5,%6,%7}, {%8,%9}, {%0,%1,%2,%3};\n"
        : "+f"(c[0]), "+f"(c[1]), "+f"(c[2]), "+f"(c[3])
        : "r"(a0), "r"(a1), "r"(a2), "r"(a3), "r"(b0), "r"(b1));
}

// ---------------- weight pre-convert (fp32 -> fp16) ----------------
__global__ void convw_kernel(const float* __restrict__ s, __half* __restrict__ d, int n4) {
    int i = blockIdx.x * blockDim.x + threadIdx.x;
    if (i >= n4) return;
    float4 v = ((const float4*)s)[i];
    __half2* dp = (__half2*)d + i * 2;
    dp[0] = __floats2half2_rn(v.x, v.y);
    dp[1] = __floats2half2_rn(v.z, v.w);
}

// ---------------- LN kernels (fp16 outputs) ----------------
__global__ void ln1_part_kernel(const float* __restrict__ w, const float* __restrict__ b,
                                int shift, const float* __restrict__ xin) {
    int gw = (blockIdx.x * blockDim.x + threadIdx.x) >> 5;
    int lane = threadIdx.x & 31;
    if (gw >= TOK) return;
    int win = gw / 49, tok = gw % 49;
    int bb = win >> 6, w64 = win & 63;
    int wh = w64 >> 3, wwi = w64 & 7;
    int ii = tok / 7, jj = tok % 7;
    int sh = (wh * 7 + ii + shift) % 56;
    int sw = (wwi * 7 + jj + shift) % 56;
    const float* base = xin ? xin : g_x;
    const float* src = base + ((size_t)bb * 3136 + sh * 56 + sw) * 192;
    float v[6];
    float s = 0.f;
#pragma unroll
    for (int q = 0; q < 6; q++) { v[q] = src[lane + q * 32]; s += v[q]; }
    s = warp_sum(s);
    float mean = s * (1.f / 192.f);
    float ss = 0.f;
#pragma unroll
    for (int q = 0; q < 6; q++) { float d = v[q] - mean; ss += d * d; }
    ss = warp_sum(ss);
    float rstd = rsqrtf(ss * (1.f / 192.f) + 1e-5f);
    __half* dst = g_hwin + (size_t)gw * 192;
#pragma unroll
    for (int q = 0; q < 6; q++) {
        int c = lane + q * 32;
        dst[c] = __float2half((v[q] - mean) * rstd * w[c] + b[c]);
    }
}

__global__ void ln2_kernel(const float* __restrict__ w, const float* __restrict__ b) {
    int gw = (blockIdx.x * blockDim.x + threadIdx.x) >> 5;
    int lane = threadIdx.x & 31;
    if (gw >= TOK) return;
    const float* src = g_x + (size_t)gw * 192;
    float v[6];
    float s = 0.f;
#pragma unroll
    for (int q = 0; q < 6; q++) { v[q] = src[lane + q * 32]; s += v[q]; }
    s = warp_sum(s);
    float mean = s * (1.f / 192.f);
    float ss = 0.f;
#pragma unroll
    for (int q = 0; q < 6; q++) { float d = v[q] - mean; ss += d * d; }
    ss = warp_sum(ss);
    float rstd = rsqrtf(ss * (1.f / 192.f) + 1e-5f);
    __half* dst = g_ln2 + (size_t)gw * 192;
#pragma unroll
    for (int q = 0; q < 6; q++) {
        int c = lane + q * 32;
        dst[c] = __float2half((v[q] - mean) * rstd * w[c] + b[c]);
    }
}

__device__ __forceinline__ int reg3(int h) { return h < 49 ? 0 : (h < 53 ? 1 : 2); }

// ---------------- tensor-core attention: one (window, head) per 128-thread CTA ----------------
__global__ void __launch_bounds__(128) attn_kernel(const float* __restrict__ rpb, int shift) {
    __shared__ __half q_sm[64 * 72];
    __shared__ __half k_sm[56 * 72];
    __shared__ __half vt_sm[32 * 72];
    __shared__ __half p_sm[64 * 72];
    __shared__ float bias_sm[169];
    int bid = blockIdx.x;
    int win = bid / 6, head = bid % 6;
    int tid = threadIdx.x;
    const __half* qg = g_q + (size_t)bid * 1568;
    const __half* kg = g_k + (size_t)bid * 1568;
    const __half* vg = g_v + (size_t)bid * 1568;

    // phase 1: zero P, Vt, and q padding rows (padding correctness)
    for (int i2 = tid; i2 < 64 * 36; i2 += 128) ((uint32_t*)p_sm)[i2] = 0;
    for (int i2 = tid; i2 < 32 * 36; i2 += 128) ((uint32_t*)vt_sm)[i2] = 0;
    for (int i2 = 49 * 36 + tid; i2 < 64 * 36; i2 += 128) ((uint32_t*)q_sm)[i2] = 0;
    __syncthreads();

    // phase 2: fill q, k (vectorized), v transposed, bias table
    for (int idx = tid; idx < 392; idx += 128) {
        int row = idx >> 3, d0 = (idx & 7) * 4;
        *(uint2*)&q_sm[row * 72 + d0] = *(const uint2*)&qg[idx * 4];
        *(uint2*)&k_sm[row * 72 + d0] = *(const uint2*)&kg[idx * 4];
    }
    for (int idx = tid; idx < 1568; idx += 128) {
        int j = idx >> 5, d = idx & 31;
        vt_sm[d * 72 + j] = vg[idx];
    }
    for (int idx = tid; idx < 169; idx += 128) bias_sm[idx] = rpb[idx * 6 + head];
    __syncthreads();

    const int wid = tid >> 5, lane = tid & 31;
    const int g = lane >> 2, tg = lane & 3;
    const int i0 = 16 * wid + g, i1 = i0 + 8;

    // S = q @ k^T : 7 n8-tiles, 2 k16-steps
    float c[7][4];
#pragma unroll
    for (int t = 0; t < 7; t++) { c[t][0] = c[t][1] = c[t][2] = c[t][3] = 0.f; }
#pragma unroll
    for (int s = 0; s < 2; s++) {
        uint32_t a0 = *(uint32_t*)&q_sm[i0 * 72 + 2 * tg + 16 * s];
        uint32_t a1 = *(uint32_t*)&q_sm[i1 * 72 + 2 * tg + 16 * s];
        uint32_t a2 = *(uint32_t*)&q_sm[i0 * 72 + 2 * tg + 8 + 16 * s];
        uint32_t a3 = *(uint32_t*)&q_sm[i1 * 72 + 2 * tg + 8 + 16 * s];
#pragma unroll
        for (int t = 0; t < 7; t++) {
            uint32_t b0 = *(uint32_t*)&k_sm[(8 * t + g) * 72 + 2 * tg + 16 * s];
            uint32_t b1 = *(uint32_t*)&k_sm[(8 * t + g) * 72 + 2 * tg + 8 + 16 * s];
            mma16816(c[t], a0, a1, a2, a3, b0, b1);
        }
    }

    // bias + mask + softmax
    int w64 = win & 63, wh = w64 >> 3, wwi = w64 & 7;
    int ic0 = i0 < 49 ? i0 : 48, ic1 = i1 < 49 ? i1 : 48;
    int yi0 = ic0 / 7, xi0 = ic0 % 7, yi1 = ic1 / 7, xi1 = ic1 % 7;
    int ri0 = 0, ri1 = 0;
    if (shift) {
        ri0 = reg3(wh * 7 + yi0) * 3 + reg3(wwi * 7 + xi0);
        ri1 = reg3(wh * 7 + yi1) * 3 + reg3(wwi * 7 + xi1);
    }
    float v0[7][2], v1[7][2];
#pragma unroll
    for (int t = 0; t < 7; t++) {
#pragma unroll
        for (int e = 0; e < 2; e++) {
            int j = 8 * t + 2 * tg + e;
            bool valid = j < 49;
            int jc = valid ? j : 0;
            int yj = jc / 7, xj = jc % 7;
            float m0 = 0.f, m1 = 0.f;
            if (shift) {
                int rj = reg3(wh * 7 + yj) * 3 + reg3(wwi * 7 + xj);
                if (ri0 != rj) m0 = -100.f;
                if (ri1 != rj) m1 = -100.f;
            }
            float b0 = bias_sm[(yi0 - yj + 6) * 13 + (xi0 - xj + 6)];
            float b1 = bias_sm[(yi1 - yj + 6) * 13 + (xi1 - xj + 6)];
            v0[t][e] = valid ? c[t][e] + b0 + m0 : -1e9f;
            v1[t][e] = valid ? c[t][2 + e] + b1 + m1 : -1e9f;
        }
    }
    float mx0 = -1e30f, mx1 = -1e30f;
#pragma unroll
    for (int t = 0; t < 7; t++) {
        mx0 = fmaxf(mx0, fmaxf(v0[t][0], v0[t][1]));
        mx1 = fmaxf(mx1, fmaxf(v1[t][0], v1[t][1]));
    }
    mx0 = fmaxf(mx0, __shfl_xor_sync(0xffffffffu, mx0, 1));
    mx0 = fmaxf(mx0, __shfl_xor_sync(0xffffffffu, mx0, 2));
    mx1 = fmaxf(mx1, __shfl_xor_sync(0xffffffffu, mx1, 1));
    mx1 = fmaxf(mx1, __shfl_xor_sync(0xffffffffu, mx1, 2));
    float sm0 = 0.f, sm1 = 0.f;
#pragma unroll
    for (int t = 0; t < 7; t++) {
#pragma unroll
        for (int e = 0; e < 2; e++) {
            v0[t][e] = __expf(v0[t][e] - mx0); sm0 += v0[t][e];
            v1[t][e] = __expf(v1[t][e] - mx1); sm1 += v1[t][e];
        }
    }
    sm0 += __shfl_xor_sync(0xffffffffu, sm0, 1);
    sm0 += __shfl_xor_sync(0xffffffffu, sm0, 2);
    sm1 += __shfl_xor_sync(0xffffffffu, sm1, 1);
    sm1 += __shfl_xor_sync(0xffffffffu, sm1, 2);
    float inv0 = 1.f / sm0, inv1 = 1.f / sm1;
#pragma unroll
    for (int t = 0; t < 7; t++) {
        *(__half2*)&p_sm[i0 * 72 + 8 * t + 2 * tg] = __floats2half2_rn(v0[t][0] * inv0, v0[t][1] * inv0);
        *(__half2*)&p_sm[i1 * 72 + 8 * t + 2 * tg] = __floats2half2_rn(v1[t][0] * inv1, v1[t][1] * inv1);
    }
    __syncthreads();

    // O = P @ V : 4 n8-tiles (d), 4 k16-steps (j)
    float o[4][4];
#pragma unroll
    for (int t = 0; t < 4; t++) { o[t][0] = o[t][1] = o[t][2] = o[t][3] = 0.f; }
#pragma unroll
    for (int s = 0; s < 4; s++) {
        uint32_t a0 = *(uint32_t*)&p_sm[i0 * 72 + 2 * tg + 16 * s];
        uint32_t a1 = *(uint32_t*)&p_sm[i1 * 72 + 2 * tg + 16 * s];
        uint32_t a2 = *(uint32_t*)&p_sm[i0 * 72 + 2 * tg + 8 + 16 * s];
        uint32_t a3 = *(uint32_t*)&p_sm[i1 * 72 + 2 * tg + 8 + 16 * s];
#pragma unroll
        for (int t = 0; t < 4; t++) {
            uint32_t b0 = *(uint32_t*)&vt_sm[(8 * t + g) * 72 + 2 * tg + 16 * s];
            uint32_t b1 = *(uint32_t*)&vt_sm[(8 * t + g) * 72 + 2 * tg + 8 + 16 * s];
            mma16816(o[t], a0, a1, a2, a3, b0, b1);
        }
    }
    if (i0 < 49) {
        __half* dst = g_attnout + ((size_t)(win * 49 + i0)) * 192 + head * 32;
#pragma unroll
        for (int t = 0; t < 4; t++)
            *(__half2*)&dst[8 * t + 2 * tg] = __floats2half2_rn(o[t][0], o[t][1]);
    }
    if (i1 < 49) {
        __half* dst = g_attnout + ((size_t)(win * 49 + i1)) * 192 + head * 32;
#pragma unroll
        for (int t = 0; t < 4; t++)
            *(__half2*)&dst[8 * t + 2 * tg] = __floats2half2_rn(o[t][2], o[t][3]);
    }
}

// -------- fp16 mma.sync GEMM: CTA 256x64, 128 threads, warp tile 64x64, 3-stage cp.async --------
// grid = (Ntiles, Mtiles): consecutive CTAs share the A M-tile (L2 reuse for FC2's 154MB A).
#define GT_DSMEM 76800

template <int MODE>
__global__ void __launch_bounds__(128) gemm_tc(const __half* __restrict__ Wt,
                                               const float* __restrict__ bias,
                                               int K, int shift,
                                               const float* __restrict__ xin,
                                               float* __restrict__ outp) {
    extern __shared__ unsigned sm[];
    const __half* A = (MODE == 0) ? g_hwin : (MODE == 1) ? g_attnout : (MODE == 2) ? g_ln2 : g_hid;
    const int bm = blockIdx.y * 256;
    const int bn = blockIdx.x * 64;
    const int tid = threadIdx.x, wid = tid >> 5, lane = tid & 31;
    const int g = lane >> 2, tg = lane & 3;
    const uint32_t sbase = smem_u32(sm);
    const __half* Abase = A + (size_t)bm * K;
    const __half* Bbase = Wt + (size_t)bn * K;
    const int NCH = K >> 5;

    float acc[4][8][4];
#pragma unroll
    for (int i = 0; i < 4; i++)
#pragma unroll
        for (int j = 0; j < 8; j++)
#pragma unroll
            for (int r = 0; r < 4; r++) acc[i][j][r] = 0.f;

    auto issue = [&](int c) {
        uint32_t sb = sbase + (c % 3) * 25600;
        const __half* Ab = Abase + c * 32;
#pragma unroll
        for (int i = 0; i < 8; i++) {
            int f8 = tid + i * 128, row = f8 >> 2, ch = f8 & 3;
            cpa16(sb + (row * 20 + ch * 4) * 4, Ab + (size_t)row * K + ch * 8);
        }
        const __half* Bb = Bbase + c * 32;
#pragma unroll
        for (int i = 0; i < 2; i++) {
            int f8 = tid + i * 128, row = f8 >> 2, ch = f8 & 3;
            cpa16(sb + 20480 + (row * 20 + ch * 4) * 4, Bb + (size_t)row * K + ch * 8);
        }
        asm volatile("cp.async.commit_group;" ::: "memory");
    };

    issue(0);
    if (NCH > 1) issue(1);
    if (NCH > 2) issue(2);

    for (int c = 0; c < NCH; c++) {
        if (c + 2 < NCH)      asm volatile("cp.async.wait_group 2;" ::: "memory");
        else if (c + 1 < NCH) asm volatile("cp.async.wait_group 1;" ::: "memory");
        else                  asm volatile("cp.async.wait_group 0;" ::: "memory");
        __syncthreads();
        const unsigned* as = sm + (c % 3) * 6400;
        const unsigned* bs = as + 5120;
#pragma unroll
        for (int s = 0; s < 2; s++) {
            const int k0 = s * 8 + tg;
            unsigned af[4][4], bf[8][2];
#pragma unroll
            for (int mt = 0; mt < 4; mt++) {
                int rb = wid * 64 + mt * 16 + g;
                af[mt][0] = as[rb * 20 + k0];
                af[mt][1] = as[(rb + 8) * 20 + k0];
                af[mt][2] = as[rb * 20 + k0 + 4];
                af[mt][3] = as[(rb + 8) * 20 + k0 + 4];
            }
#pragma unroll
            for (int nt = 0; nt < 8; nt++) {
                int nb = nt * 8 + g;
                bf[nt][0] = bs[nb * 20 + k0];
                bf[nt][1] = bs[nb * 20 + k0 + 4];
            }
#pragma unroll
            for (int mt = 0; mt < 4; mt++)
#pragma unroll
                for (int nt = 0; nt < 8; nt++)
                    mma16816(acc[mt][nt], af[mt][0], af[mt][1], af[mt][2], af[mt][3],
                             bf[nt][0], bf[nt][1]);
        }
        __syncthreads();
        if (c + 3 < NCH) issue(c + 3);
    }

#pragma unroll
    for (int mt = 0; mt < 4; mt++)
#pragma unroll
        for (int rr = 0; rr < 2; rr++) {
            int m = bm + wid * 64 + mt * 16 + g + rr * 8;
            if (MODE == 0) {
                int win = m / 49, tok = m % 49;
#pragma unroll
                for (int nt = 0; nt < 8; nt++) {
                    int c0 = nt * 8 + tg * 2;
                    int n = bn + c0;
                    int part = n / 192, rem = n % 192, head = rem >> 5, dd = rem & 31;
                    size_t dst = ((size_t)(win * 6 + head) * 49 + tok) * 32 + dd;
                    float v0 = acc[mt][nt][rr * 2] + bias[n];
                    float v1 = acc[mt][nt][rr * 2 + 1] + bias[n + 1];
                    if (part == 0)      *(__half2*)(g_q + dst) = __floats2half2_rn(v0 * SCALE, v1 * SCALE);
                    else if (part == 1) *(__half2*)(g_k + dst) = __floats2half2_rn(v0, v1);
                    else                *(__half2*)(g_v + dst) = __floats2half2_rn(v0, v1);
                }
            } else if (MODE == 1) {
                int win = m / 49, tok = m % 49;
                int bb = win >> 6, w64 = win & 63, wh = w64 >> 3, wwi = w64 & 7;
                int ii = tok / 7, jj = tok % 7;
                int hh = wh * 7 + ii, gc = wwi * 7 + jj;
                if (shift) { hh = (hh + 7) % 56; gc = (gc + 7) % 56; }
                size_t rowo = ((size_t)bb * 3136 + hh * 56 + gc) * 192 + bn;
                const float* resp = (xin ? xin : (const float*)g_x) + rowo;
#pragma unroll
                for (int nt = 0; nt < 8; nt++) {
                    int c0 = nt * 8 + tg * 2;
                    float2 rv = *(const float2*)(resp + c0);
                    float2 bv = *(const float2*)(bias + bn + c0);
                    float v0 = acc[mt][nt][rr * 2] + bv.x + rv.x;
                    float v1 = acc[mt][nt][rr * 2 + 1] + bv.y + rv.y;
                    *(float2*)(g_x + rowo + c0) = make_float2(v0, v1);
                }
            } else if (MODE == 2) {
                __half* hrow = g_hid + (size_t)m * 768 + bn;
#pragma unroll
                for (int nt = 0; nt < 8; nt++) {
                    int c0 = nt * 8 + tg * 2;
                    float2 bv = *(const float2*)(bias + bn + c0);
                    float v0 = acc[mt][nt][rr * 2] + bv.x;
                    float v1 = acc[mt][nt][rr * 2 + 1] + bv.y;
                    v0 = v0 * 0.5f * (1.f + erff(v0 * 0.70710678118654752f));
                    v1 = v1 * 0.5f * (1.f + erff(v1 * 0.70710678118654752f));
                    *(__half2*)(hrow + c0) = __floats2half2_rn(v0, v1);
                }
            } else {
                size_t rowo = (size_t)m * 192 + bn;
                float* dst = outp ? outp : g_x;
#pragma unroll
                for (int nt = 0; nt < 8; nt++) {
                    int c0 = nt * 8 + tg * 2;
                    float2 rv = *(const float2*)(g_x + rowo + c0);
                    float2 bv = *(const float2*)(bias + bn + c0);
                    float v0 = acc[mt][nt][rr * 2] + bv.x + rv.x;
                    float v1 = acc[mt][nt][rr * 2 + 1] + bv.y + rv.y;
                    *(float2*)(dst + rowo + c0) = make_float2(v0, v1);
                }
            }
        }
}

extern "C" void kernel_launch(void* const* d_in, const int* in_sizes, int n_in,
                              void* d_out, int out_size) {
    const float* x     = (const float*)d_in[0];
    const float* n1w   = (const float*)d_in[1];
    const float* n1b   = (const float*)d_in[2];
    const float* qkvw  = (const float*)d_in[3];
    const float* qkvb  = (const float*)d_in[4];
    const float* rpb   = (const float*)d_in[5];
    const float* projw = (const float*)d_in[6];
    const float* projb = (const float*)d_in[7];
    const float* n2w   = (const float*)d_in[8];
    const float* n2b   = (const float*)d_in[9];
    const float* f1w   = (const float*)d_in[10];
    const float* f1b   = (const float*)d_in[11];
    const float* f2w   = (const float*)d_in[12];
    const float* f2b   = (const float*)d_in[13];

    cudaFuncSetAttribute(gemm_tc<0>, cudaFuncAttributeMaxDynamicSharedMemorySize, GT_DSMEM);
    cudaFuncSetAttribute(gemm_tc<1>, cudaFuncAttributeMaxDynamicSharedMemorySize, GT_DSMEM);
    cudaFuncSetAttribute(gemm_tc<2>, cudaFuncAttributeMaxDynamicSharedMemorySize, GT_DSMEM);
    cudaFuncSetAttribute(gemm_tc<3>, cudaFuncAttributeMaxDynamicSharedMemorySize, GT_DSMEM);

    __half* wq = nullptr; cudaGetSymbolAddress((void**)&wq, g_wcv);
    __half* wp = wq + 221184;
    __half* w1 = wq + 294912;
    __half* w2 = wq + 589824;
    convw_kernel<<<216, 256>>>(qkvw,  wq, 55296);
    convw_kernel<<<72,  256>>>(projw, wp, 18432);
    convw_kernel<<<288, 256>>>(f1w,   w1, 73728);
    convw_kernel<<<288, 256>>>(f2w,   w2, 73728);

    for (int d = 0; d < 2; d++) {
        int shift = d ? 3 : 0;
        const float* xin = (d == 0) ? x : nullptr;
        float* outp = (d == 1) ? (float*)d_out : nullptr;
        ln1_part_kernel<<<12544, 256>>>(n1w + d * 192, n1b + d * 192, shift, xin);
        gemm_tc<0><<<dim3(9, 392), 128, GT_DSMEM>>>(wq + (size_t)d * 110592, qkvb + d * 576, 192, 0, nullptr, nullptr);
        attn_kernel<<<12288, 128>>>(rpb + d * 169 * 6, shift);
        gemm_tc<1><<<dim3(3, 392), 128, GT_DSMEM>>>(wp + (size_t)d * 36864, projb + d * 192, 192, shift, xin, nullptr);
        ln2_kernel<<<12544, 256>>>(n2w + d * 192, n2b + d * 192);
        gemm_tc<2><<<dim3(12, 392), 128, GT_DSMEM>>>(w1 + (size_t)d * 147456, f1b + d * 768, 192, 0, nullptr, nullptr);
        gemm_tc<3><<<dim3(3, 392), 128, GT_DSMEM>>>(w2 + (size_t)d * 147456, f2b + d * 192, 768, 0, nullptr, outp);
    }
}

// round 14
// speedup vs baseline: 1.1148x; 1.0860x over previous
#include <cuda_runtime.h>
#include <cuda_fp16.h>
#include <math.h>
#include <stdint.h>

#define TOK 100352
#define SCALE 0.17677669529663687f

__device__ float  g_x[19267584];        // fp32 residual stream
__device__ __half g_hwin[19267584];
__device__ __half g_q[19267584];
__device__ __half g_k[19267584];
__device__ __half g_v[19267584];
__device__ __half g_attnout[19267584];
__device__ __half g_ln2[19267584];
__device__ __half g_hid[77070336];
__device__ __half g_wcv[884736];        // fp16 weights: qkv|proj|f1|f2 (both layers)

__device__ __forceinline__ float warp_sum(float v) {
#pragma unroll
    for (int o = 16; o; o >>= 1) v += __shfl_xor_sync(0xffffffffu, v, o);
    return v;
}
__device__ __forceinline__ uint32_t smem_u32(const void* p) {
    uint32_t a;
    asm("{ .reg .u64 t; cvta.to.shared.u64 t, %1; cvt.u32.u64 %0, t; }" : "=r"(a) : "l"(p));
    return a;
}
__device__ __forceinline__ void cpa16(uint32_t dst, const void* src) {
    asm volatile("cp.async.cg.shared.global [%0], [%1], 16;" :: "r"(dst), "l"(src));
}
__device__ __forceinline__ void mma16816(float* c, uint32_t a0, uint32_t a1, uint32_t a2, uint32_t a3,
                                         uint32_t b0, uint32_t b1) {
    asm volatile(
        "mma.sync.aligned.m16n8k16.row.col.f32.f16.f16.f32 "
        "{%0,%1,%2,%3}, {%4,%5,%6,%7}, {%8,%9}, {%0,%1,%2,%3};\n"
        : "+f"(c[0]), "+f"(c[1]), "+f"(c[2]), "+f"(c[3])
        : "r"(a0), "r"(a1), "r"(a2), "r"(a3), "r"(b0), "r"(b1));
}

// ---------------- weight pre-convert (fp32 -> fp16) ----------------
__global__ void convw_kernel(const float* __restrict__ s, __half* __restrict__ d, int n4) {
    int i = blockIdx.x * blockDim.x + threadIdx.x;
    if (i >= n4) return;
    float4 v = ((const float4*)s)[i];
    __half2* dp = (__half2*)d + i * 2;
    dp[0] = __floats2half2_rn(v.x, v.y);
    dp[1] = __floats2half2_rn(v.z, v.w);
}

// ---------------- LN kernels (fp16 outputs) ----------------
__global__ void ln1_part_kernel(const float* __restrict__ w, const float* __restrict__ b,
                                int shift, const float* __restrict__ xin) {
    int gw = (blockIdx.x * blockDim.x + threadIdx.x) >> 5;
    int lane = threadIdx.x & 31;
    if (gw >= TOK) return;
    int win = gw / 49, tok = gw % 49;
    int bb = win >> 6, w64 = win & 63;
    int wh = w64 >> 3, wwi = w64 & 7;
    int ii = tok / 7, jj = tok % 7;
    int sh = (wh * 7 + ii + shift) % 56;
    int sw = (wwi * 7 + jj + shift) % 56;
    const float* base = xin ? xin : g_x;
    const float* src = base + ((size_t)bb * 3136 + sh * 56 + sw) * 192;
    float v[6];
    float s = 0.f;
#pragma unroll
    for (int q = 0; q < 6; q++) { v[q] = src[lane + q * 32]; s += v[q]; }
    s = warp_sum(s);
    float mean = s * (1.f / 192.f);
    float ss = 0.f;
#pragma unroll
    for (int q = 0; q < 6; q++) { float d = v[q] - mean; ss += d * d; }
    ss = warp_sum(ss);
    float rstd = rsqrtf(ss * (1.f / 192.f) + 1e-5f);
    __half* dst = g_hwin + (size_t)gw * 192;
#pragma unroll
    for (int q = 0; q < 6; q++) {
        int c = lane + q * 32;
        dst[c] = __float2half((v[q] - mean) * rstd * w[c] + b[c]);
    }
}

__global__ void ln2_kernel(const float* __restrict__ w, const float* __restrict__ b) {
    int gw = (blockIdx.x * blockDim.x + threadIdx.x) >> 5;
    int lane = threadIdx.x & 31;
    if (gw >= TOK) return;
    const float* src = g_x + (size_t)gw * 192;
    float v[6];
    float s = 0.f;
#pragma unroll
    for (int q = 0; q < 6; q++) { v[q] = src[lane + q * 32]; s += v[q]; }
    s = warp_sum(s);
    float mean = s * (1.f / 192.f);
    float ss = 0.f;
#pragma unroll
    for (int q = 0; q < 6; q++) { float d = v[q] - mean; ss += d * d; }
    ss = warp_sum(ss);
    float rstd = rsqrtf(ss * (1.f / 192.f) + 1e-5f);
    __half* dst = g_ln2 + (size_t)gw * 192;
#pragma unroll
    for (int q = 0; q < 6; q++) {
        int c = lane + q * 32;
        dst[c] = __float2half((v[q] - mean) * rstd * w[c] + b[c]);
    }
}

__device__ __forceinline__ int reg3(int h) { return h < 49 ? 0 : (h < 53 ? 1 : 2); }

// ---------------- tensor-core attention: one (window, head) per 128-thread CTA ----------------
__global__ void __launch_bounds__(128) attn_kernel(const float* __restrict__ rpb, int shift) {
    __shared__ __half q_sm[64 * 72];
    __shared__ __half k_sm[56 * 72];
    __shared__ __half vt_sm[32 * 72];
    __shared__ __half p_sm[64 * 72];
    __shared__ float bias_sm[169];
    int bid = blockIdx.x;
    int win = bid / 6, head = bid % 6;
    int tid = threadIdx.x;
    const __half* qg = g_q + (size_t)bid * 1568;
    const __half* kg = g_k + (size_t)bid * 1568;
    const __half* vg = g_v + (size_t)bid * 1568;

    // phase 1: zero P, Vt, and q padding rows (padding correctness)
    for (int i2 = tid; i2 < 64 * 36; i2 += 128) ((uint32_t*)p_sm)[i2] = 0;
    for (int i2 = tid; i2 < 32 * 36; i2 += 128) ((uint32_t*)vt_sm)[i2] = 0;
    for (int i2 = 49 * 36 + tid; i2 < 64 * 36; i2 += 128) ((uint32_t*)q_sm)[i2] = 0;
    __syncthreads();

    // phase 2: fill q, k (vectorized), v transposed, bias table
    for (int idx = tid; idx < 392; idx += 128) {
        int row = idx >> 3, d0 = (idx & 7) * 4;
        *(uint2*)&q_sm[row * 72 + d0] = *(const uint2*)&qg[idx * 4];
        *(uint2*)&k_sm[row * 72 + d0] = *(const uint2*)&kg[idx * 4];
    }
    for (int idx = tid; idx < 1568; idx += 128) {
        int j = idx >> 5, d = idx & 31;
        vt_sm[d * 72 + j] = vg[idx];
    }
    for (int idx = tid; idx < 169; idx += 128) bias_sm[idx] = rpb[idx * 6 + head];
    __syncthreads();

    const int wid = tid >> 5, lane = tid & 31;
    const int g = lane >> 2, tg = lane & 3;
    const int i0 = 16 * wid + g, i1 = i0 + 8;

    // S = q @ k^T : 7 n8-tiles, 2 k16-steps
    float c[7][4];
#pragma unroll
    for (int t = 0; t < 7; t++) { c[t][0] = c[t][1] = c[t][2] = c[t][3] = 0.f; }
#pragma unroll
    for (int s = 0; s < 2; s++) {
        uint32_t a0 = *(uint32_t*)&q_sm[i0 * 72 + 2 * tg + 16 * s];
        uint32_t a1 = *(uint32_t*)&q_sm[i1 * 72 + 2 * tg + 16 * s];
        uint32_t a2 = *(uint32_t*)&q_sm[i0 * 72 + 2 * tg + 8 + 16 * s];
        uint32_t a3 = *(uint32_t*)&q_sm[i1 * 72 + 2 * tg + 8 + 16 * s];
#pragma unroll
        for (int t = 0; t < 7; t++) {
            uint32_t b0 = *(uint32_t*)&k_sm[(8 * t + g) * 72 + 2 * tg + 16 * s];
            uint32_t b1 = *(uint32_t*)&k_sm[(8 * t + g) * 72 + 2 * tg + 8 + 16 * s];
            mma16816(c[t], a0, a1, a2, a3, b0, b1);
        }
    }

    // bias + mask + softmax
    int w64 = win & 63, wh = w64 >> 3, wwi = w64 & 7;
    int ic0 = i0 < 49 ? i0 : 48, ic1 = i1 < 49 ? i1 : 48;
    int yi0 = ic0 / 7, xi0 = ic0 % 7, yi1 = ic1 / 7, xi1 = ic1 % 7;
    int ri0 = 0, ri1 = 0;
    if (shift) {
        ri0 = reg3(wh * 7 + yi0) * 3 + reg3(wwi * 7 + xi0);
        ri1 = reg3(wh * 7 + yi1) * 3 + reg3(wwi * 7 + xi1);
    }
    float v0[7][2], v1[7][2];
#pragma unroll
    for (int t = 0; t < 7; t++) {
#pragma unroll
        for (int e = 0; e < 2; e++) {
            int j = 8 * t + 2 * tg + e;
            bool valid = j < 49;
            int jc = valid ? j : 0;
            int yj = jc / 7, xj = jc % 7;
            float m0 = 0.f, m1 = 0.f;
            if (shift) {
                int rj = reg3(wh * 7 + yj) * 3 + reg3(wwi * 7 + xj);
                if (ri0 != rj) m0 = -100.f;
                if (ri1 != rj) m1 = -100.f;
            }
            float b0 = bias_sm[(yi0 - yj + 6) * 13 + (xi0 - xj + 6)];
            float b1 = bias_sm[(yi1 - yj + 6) * 13 + (xi1 - xj + 6)];
            v0[t][e] = valid ? c[t][e] + b0 + m0 : -1e9f;
            v1[t][e] = valid ? c[t][2 + e] + b1 + m1 : -1e9f;
        }
    }
    float mx0 = -1e30f, mx1 = -1e30f;
#pragma unroll
    for (int t = 0; t < 7; t++) {
        mx0 = fmaxf(mx0, fmaxf(v0[t][0], v0[t][1]));
        mx1 = fmaxf(mx1, fmaxf(v1[t][0], v1[t][1]));
    }
    mx0 = fmaxf(mx0, __shfl_xor_sync(0xffffffffu, mx0, 1));
    mx0 = fmaxf(mx0, __shfl_xor_sync(0xffffffffu, mx0, 2));
    mx1 = fmaxf(mx1, __shfl_xor_sync(0xffffffffu, mx1, 1));
    mx1 = fmaxf(mx1, __shfl_xor_sync(0xffffffffu, mx1, 2));
    float sm0 = 0.f, sm1 = 0.f;
#pragma unroll
    for (int t = 0; t < 7; t++) {
#pragma unroll
        for (int e = 0; e < 2; e++) {
            v0[t][e] = __expf(v0[t][e] - mx0); sm0 += v0[t][e];
            v1[t][e] = __expf(v1[t][e] - mx1); sm1 += v1[t][e];
        }
    }
    sm0 += __shfl_xor_sync(0xffffffffu, sm0, 1);
    sm0 += __shfl_xor_sync(0xffffffffu, sm0, 2);
    sm1 += __shfl_xor_sync(0xffffffffu, sm1, 1);
    sm1 += __shfl_xor_sync(0xffffffffu, sm1, 2);
    float inv0 = 1.f / sm0, inv1 = 1.f / sm1;
#pragma unroll
    for (int t = 0; t < 7; t++) {
        *(__half2*)&p_sm[i0 * 72 + 8 * t + 2 * tg] = __floats2half2_rn(v0[t][0] * inv0, v0[t][1] * inv0);
        *(__half2*)&p_sm[i1 * 72 + 8 * t + 2 * tg] = __floats2half2_rn(v1[t][0] * inv1, v1[t][1] * inv1);
    }
    __syncthreads();

    // O = P @ V : 4 n8-tiles (d), 4 k16-steps (j)
    float o[4][4];
#pragma unroll
    for (int t = 0; t < 4; t++) { o[t][0] = o[t][1] = o[t][2] = o[t][3] = 0.f; }
#pragma unroll
    for (int s = 0; s < 4; s++) {
        uint32_t a0 = *(uint32_t*)&p_sm[i0 * 72 + 2 * tg + 16 * s];
        uint32_t a1 = *(uint32_t*)&p_sm[i1 * 72 + 2 * tg + 16 * s];
        uint32_t a2 = *(uint32_t*)&p_sm[i0 * 72 + 2 * tg + 8 + 16 * s];
        uint32_t a3 = *(uint32_t*)&p_sm[i1 * 72 + 2 * tg + 8 + 16 * s];
#pragma unroll
        for (int t = 0; t < 4; t++) {
            uint32_t b0 = *(uint32_t*)&vt_sm[(8 * t + g) * 72 + 2 * tg + 16 * s];
            uint32_t b1 = *(uint32_t*)&vt_sm[(8 * t + g) * 72 + 2 * tg + 8 + 16 * s];
            mma16816(o[t], a0, a1, a2, a3, b0, b1);
        }
    }
    if (i0 < 49) {
        __half* dst = g_attnout + ((size_t)(win * 49 + i0)) * 192 + head * 32;
#pragma unroll
        for (int t = 0; t < 4; t++)
            *(__half2*)&dst[8 * t + 2 * tg] = __floats2half2_rn(o[t][0], o[t][1]);
    }
    if (i1 < 49) {
        __half* dst = g_attnout + ((size_t)(win * 49 + i1)) * 192 + head * 32;
#pragma unroll
        for (int t = 0; t < 4; t++)
            *(__half2*)&dst[8 * t + 2 * tg] = __floats2half2_rn(o[t][2], o[t][3]);
    }
}

// -------- fp16 mma.sync GEMM: CTA 256x64, 128 threads, warp tile 64x64, 2-stage cp.async --------
// __launch_bounds__(128, 3): force <=170 regs -> 3 CTAs/SM = 12 warps.
#define GT_DSMEM 51200

template <int MODE>
__global__ void __launch_bounds__(128, 3) gemm_tc(const __half* __restrict__ Wt,
                                                  const float* __restrict__ bias,
                                                  int K, int shift,
                                                  const float* __restrict__ xin,
                                                  float* __restrict__ outp) {
    extern __shared__ unsigned sm[];
    const __half* A = (MODE == 0) ? g_hwin : (MODE == 1) ? g_attnout : (MODE == 2) ? g_ln2 : g_hid;
    const int bm = blockIdx.x * 256;
    const int bn = blockIdx.y * 64;
    const int tid = threadIdx.x, wid = tid >> 5, lane = tid & 31;
    const int g = lane >> 2, tg = lane & 3;
    const uint32_t sbase = smem_u32(sm);
    const __half* Abase = A + (size_t)bm * K;
    const __half* Bbase = Wt + (size_t)bn * K;
    const int NCH = K >> 5;

    float acc[4][8][4];
#pragma unroll
    for (int i = 0; i < 4; i++)
#pragma unroll
        for (int j = 0; j < 8; j++)
#pragma unroll
            for (int r = 0; r < 4; r++) acc[i][j][r] = 0.f;

    auto issue = [&](int c) {
        uint32_t sb = sbase + (c & 1) * 25600;
        const __half* Ab = Abase + c * 32;
#pragma unroll
        for (int i = 0; i < 8; i++) {
            int f8 = tid + i * 128, row = f8 >> 2, ch = f8 & 3;
            cpa16(sb + (row * 20 + ch * 4) * 4, Ab + (size_t)row * K + ch * 8);
        }
        const __half* Bb = Bbase + c * 32;
#pragma unroll
        for (int i = 0; i < 2; i++) {
            int f8 = tid + i * 128, row = f8 >> 2, ch = f8 & 3;
            cpa16(sb + 20480 + (row * 20 + ch * 4) * 4, Bb + (size_t)row * K + ch * 8);
        }
        asm volatile("cp.async.commit_group;" ::: "memory");
    };

    issue(0);
    if (NCH > 1) issue(1);

    for (int c = 0; c < NCH; c++) {
        if (c + 1 < NCH) asm volatile("cp.async.wait_group 1;" ::: "memory");
        else             asm volatile("cp.async.wait_group 0;" ::: "memory");
        __syncthreads();
        const unsigned* as = sm + (c & 1) * 6400;
        const unsigned* bs = as + 5120;
#pragma unroll
        for (int s = 0; s < 2; s++) {
            const int k0 = s * 8 + tg;
            unsigned af[4][4], bf[8][2];
#pragma unroll
            for (int mt = 0; mt < 4; mt++) {
                int rb = wid * 64 + mt * 16 + g;
                af[mt][0] = as[rb * 20 + k0];
                af[mt][1] = as[(rb + 8) * 20 + k0];
                af[mt][2] = as[rb * 20 + k0 + 4];
                af[mt][3] = as[(rb + 8) * 20 + k0 + 4];
            }
#pragma unroll
            for (int nt = 0; nt < 8; nt++) {
                int nb = nt * 8 + g;
                bf[nt][0] = bs[nb * 20 + k0];
                bf[nt][1] = bs[nb * 20 + k0 + 4];
            }
#pragma unroll
            for (int mt = 0; mt < 4; mt++)
#pragma unroll
                for (int nt = 0; nt < 8; nt++)
                    mma16816(acc[mt][nt], af[mt][0], af[mt][1], af[mt][2], af[mt][3],
                             bf[nt][0], bf[nt][1]);
        }
        __syncthreads();
        if (c + 2 < NCH) issue(c + 2);
    }

#pragma unroll
    for (int mt = 0; mt < 4; mt++)
#pragma unroll
        for (int rr = 0; rr < 2; rr++) {
            int m = bm + wid * 64 + mt * 16 + g + rr * 8;
            if (MODE == 0) {
                int win = m / 49, tok = m % 49;
#pragma unroll
                for (int nt = 0; nt < 8; nt++) {
                    int c0 = nt * 8 + tg * 2;
                    int n = bn + c0;
                    int part = n / 192, rem = n % 192, head = rem >> 5, dd = rem & 31;
                    size_t dst = ((size_t)(win * 6 + head) * 49 + tok) * 32 + dd;
                    float v0 = acc[mt][nt][rr * 2] + bias[n];
                    float v1 = acc[mt][nt][rr * 2 + 1] + bias[n + 1];
                    if (part == 0)      *(__half2*)(g_q + dst) = __floats2half2_rn(v0 * SCALE, v1 * SCALE);
                    else if (part == 1) *(__half2*)(g_k + dst) = __floats2half2_rn(v0, v1);
                    else                *(__half2*)(g_v + dst) = __floats2half2_rn(v0, v1);
                }
            } else if (MODE == 1) {
                int win = m / 49, tok = m % 49;
                int bb = win >> 6, w64 = win & 63, wh = w64 >> 3, wwi = w64 & 7;
                int ii = tok / 7, jj = tok % 7;
                int hh = wh * 7 + ii, gc = wwi * 7 + jj;
                if (shift) { hh = (hh + 7) % 56; gc = (gc + 7) % 56; }
                size_t rowo = ((size_t)bb * 3136 + hh * 56 + gc) * 192 + bn;
                const float* resp = (xin ? xin : (const float*)g_x) + rowo;
#pragma unroll
                for (int nt = 0; nt < 8; nt++) {
                    int c0 = nt * 8 + tg * 2;
                    float2 rv = *(const float2*)(resp + c0);
                    float2 bv = *(const float2*)(bias + bn + c0);
                    float v0 = acc[mt][nt][rr * 2] + bv.x + rv.x;
                    float v1 = acc[mt][nt][rr * 2 + 1] + bv.y + rv.y;
                    *(float2*)(g_x + rowo + c0) = make_float2(v0, v1);
                }
            } else if (MODE == 2) {
                __half* hrow = g_hid + (size_t)m * 768 + bn;
#pragma unroll
                for (int nt = 0; nt < 8; nt++) {
                    int c0 = nt * 8 + tg * 2;
                    float2 bv = *(const float2*)(bias + bn + c0);
                    float v0 = acc[mt][nt][rr * 2] + bv.x;
                    float v1 = acc[mt][nt][rr * 2 + 1] + bv.y;
                    v0 = v0 * 0.5f * (1.f + erff(v0 * 0.70710678118654752f));
                    v1 = v1 * 0.5f * (1.f + erff(v1 * 0.70710678118654752f));
                    *(__half2*)(hrow + c0) = __floats2half2_rn(v0, v1);
                }
            } else {
                size_t rowo = (size_t)m * 192 + bn;
                float* dst = outp ? outp : g_x;
#pragma unroll
                for (int nt = 0; nt < 8; nt++) {
                    int c0 = nt * 8 + tg * 2;
                    float2 rv = *(const float2*)(g_x + rowo + c0);
                    float2 bv = *(const float2*)(bias + bn + c0);
                    float v0 = acc[mt][nt][rr * 2] + bv.x + rv.x;
                    float v1 = acc[mt][nt][rr * 2 + 1] + bv.y + rv.y;
                    *(float2*)(dst + rowo + c0) = make_float2(v0, v1);
                }
            }
        }
}

extern "C" void kernel_launch(void* const* d_in, const int* in_sizes, int n_in,
                              void* d_out, int out_size) {
    const float* x     = (const float*)d_in[0];
    const float* n1w   = (const float*)d_in[1];
    const float* n1b   = (const float*)d_in[2];
    const float* qkvw  = (const float*)d_in[3];
    const float* qkvb  = (const float*)d_in[4];
    const float* rpb   = (const float*)d_in[5];
    const float* projw = (const float*)d_in[6];
    const float* projb = (const float*)d_in[7];
    const float* n2w   = (const float*)d_in[8];
    const float* n2b   = (const float*)d_in[9];
    const float* f1w   = (const float*)d_in[10];
    const float* f1b   = (const float*)d_in[11];
    const float* f2w   = (const float*)d_in[12];
    const float* f2b   = (const float*)d_in[13];

    cudaFuncSetAttribute(gemm_tc<0>, cudaFuncAttributeMaxDynamicSharedMemorySize, GT_DSMEM);
    cudaFuncSetAttribute(gemm_tc<1>, cudaFuncAttributeMaxDynamicSharedMemorySize, GT_DSMEM);
    cudaFuncSetAttribute(gemm_tc<2>, cudaFuncAttributeMaxDynamicSharedMemorySize, GT_DSMEM);
    cudaFuncSetAttribute(gemm_tc<3>, cudaFuncAttributeMaxDynamicSharedMemorySize, GT_DSMEM);

    __half* wq = nullptr; cudaGetSymbolAddress((void**)&wq, g_wcv);
    __half* wp = wq + 221184;
    __half* w1 = wq + 294912;
    __half* w2 = wq + 589824;
    convw_kernel<<<216, 256>>>(qkvw,  wq, 55296);
    convw_kernel<<<72,  256>>>(projw, wp, 18432);
    convw_kernel<<<288, 256>>>(f1w,   w1, 73728);
    convw_kernel<<<288, 256>>>(f2w,   w2, 73728);

    for (int d = 0; d < 2; d++) {
        int shift = d ? 3 : 0;
        const float* xin = (d == 0) ? x : nullptr;
        float* outp = (d == 1) ? (float*)d_out : nullptr;
        ln1_part_kernel<<<12544, 256>>>(n1w + d * 192, n1b + d * 192, shift, xin);
        gemm_tc<0><<<dim3(392, 9), 128, GT_DSMEM>>>(wq + (size_t)d * 110592, qkvb + d * 576, 192, 0, nullptr, nullptr);
        attn_kernel<<<12288, 128>>>(rpb + d * 169 * 6, shift);
        gemm_tc<1><<<dim3(392, 3), 128, GT_DSMEM>>>(wp + (size_t)d * 36864, projb + d * 192, 192, shift, xin, nullptr);
        ln2_kernel<<<12544, 256>>>(n2w + d * 192, n2b + d * 192);
        gemm_tc<2><<<dim3(392, 12), 128, GT_DSMEM>>>(w1 + (size_t)d * 147456, f1b + d * 768, 192, 0, nullptr, nullptr);
        gemm_tc<3><<<dim3(392, 3), 128, GT_DSMEM>>>(w2 + (size_t)d * 147456, f2b + d * 192, 768, 0, nullptr, outp);
    }
}